// round 1
// baseline (speedup 1.0000x reference)
#include <cuda_runtime.h>

#define SEQ 4096
#define DIM 1024
#define NH  16
#define HS  64
#define PAD 68   // smem row stride (floats): 4-aligned for float4, breaks bank patterns

// Scratch (device globals: no allocation allowed in kernel_launch)
__device__ float g_q[NH * SEQ * HS];
__device__ float g_k[NH * SEQ * HS];
__device__ float g_v[NH * SEQ * HS];
__device__ float g_att[SEQ * DIM];

// ---------------------------------------------------------------------------
// C = A @ W^T + bias.  A: [4096, 1024] row-major, W: [N=1024, K=1024] row-major
// (torch Linear semantics).  HEADMAJOR: write C in [head][s][hs] layout.
// 128x128 tile, BK=8, 256 threads, 8x8 per-thread micro-tile.
// ---------------------------------------------------------------------------
template <bool HEADMAJOR>
__global__ __launch_bounds__(256, 2)
void gemm_bias_kernel(const float* __restrict__ A,
                      const float* __restrict__ W,
                      const float* __restrict__ bias,
                      float* __restrict__ C)
{
    __shared__ float As[8][128];
    __shared__ float Bs[8][128];

    const int bm  = blockIdx.y * 128;
    const int bn  = blockIdx.x * 128;
    const int tid = threadIdx.x;
    const int ty  = tid >> 4;        // 0..15
    const int tx  = tid & 15;        // 0..15
    const int lrow = tid >> 1;       // 0..127
    const int lc4  = (tid & 1) * 4;  // 0 or 4

    float acc[8][8];
#pragma unroll
    for (int i = 0; i < 8; i++)
#pragma unroll
        for (int j = 0; j < 8; j++) acc[i][j] = 0.f;

    const float* Ap = A + (bm + lrow) * DIM + lc4;
    const float* Wp = W + (bn + lrow) * DIM + lc4;

    for (int k0 = 0; k0 < DIM; k0 += 8) {
        float4 a4 = *(const float4*)(Ap + k0);
        float4 b4 = *(const float4*)(Wp + k0);
        __syncthreads();   // previous iteration's compute done before overwrite
        As[lc4 + 0][lrow] = a4.x; As[lc4 + 1][lrow] = a4.y;
        As[lc4 + 2][lrow] = a4.z; As[lc4 + 3][lrow] = a4.w;
        Bs[lc4 + 0][lrow] = b4.x; Bs[lc4 + 1][lrow] = b4.y;
        Bs[lc4 + 2][lrow] = b4.z; Bs[lc4 + 3][lrow] = b4.w;
        __syncthreads();
#pragma unroll
        for (int k = 0; k < 8; k++) {
            float4 a0 = *(const float4*)&As[k][ty * 8];
            float4 a1 = *(const float4*)&As[k][ty * 8 + 4];
            float4 b0 = *(const float4*)&Bs[k][tx * 8];
            float4 b1 = *(const float4*)&Bs[k][tx * 8 + 4];
            float av[8] = {a0.x, a0.y, a0.z, a0.w, a1.x, a1.y, a1.z, a1.w};
            float bv[8] = {b0.x, b0.y, b0.z, b0.w, b1.x, b1.y, b1.z, b1.w};
#pragma unroll
            for (int i = 0; i < 8; i++)
#pragma unroll
                for (int j = 0; j < 8; j++)
                    acc[i][j] = fmaf(av[i], bv[j], acc[i][j]);
        }
    }

    float bb[8];
#pragma unroll
    for (int j = 0; j < 8; j++) bb[j] = bias[bn + tx * 8 + j];

#pragma unroll
    for (int i = 0; i < 8; i++) {
        const int row = bm + ty * 8 + i;
#pragma unroll
        for (int j = 0; j < 8; j++) acc[i][j] += bb[j];
        if (HEADMAJOR) {
            // col block tx*8..tx*8+7 is 8-aligned -> never crosses a 64 (head) boundary
            const int c0   = bn + tx * 8;
            const int head = c0 >> 6;
            const int off  = c0 & 63;
            float* dst = C + ((size_t)head * SEQ + row) * HS + off;
            *(float4*)dst       = make_float4(acc[i][0], acc[i][1], acc[i][2], acc[i][3]);
            *(float4*)(dst + 4) = make_float4(acc[i][4], acc[i][5], acc[i][6], acc[i][7]);
        } else {
            float* dst = C + (size_t)row * DIM + bn + tx * 8;
            *(float4*)dst       = make_float4(acc[i][0], acc[i][1], acc[i][2], acc[i][3]);
            *(float4*)(dst + 4) = make_float4(acc[i][4], acc[i][5], acc[i][6], acc[i][7]);
        }
    }
}

// ---------------------------------------------------------------------------
// Causal flash attention, fp32.  One CTA = one (head, 64-row Q tile).
// Online softmax over 64-col K tiles, kt = 0..qt only.
// Thread (ty,tx) in a 16x16 layout owns a 4x4 micro-tile.
// ---------------------------------------------------------------------------
__global__ __launch_bounds__(256, 2)
void attn_kernel()
{
    extern __shared__ float sm[];
    float* Qs = sm;                 // [d][q]  (transposed), stride PAD
    float* Ks = sm + 1 * 64 * PAD;  // [d][k]  (transposed)
    float* Vs = sm + 2 * 64 * PAD;  // [k][d]  (natural)
    float* Ps = sm + 3 * 64 * PAD;  // [k][q]  (transposed P)

    const int head = blockIdx.y;
    const int qt   = 63 - blockIdx.x;   // heavy CTAs dispatched first
    const int tid  = threadIdx.x;
    const int ty   = tid >> 4;
    const int tx   = tid & 15;
    const int lr   = tid >> 2;          // 0..63
    const int lc4  = (tid & 3) * 4;     // 0,4,8,12

    const float* Qg = g_q + ((size_t)head * SEQ + qt * 64) * HS;
    const float* Kg = g_k + (size_t)head * SEQ * HS;
    const float* Vg = g_v + (size_t)head * SEQ * HS;

    // Load Q tile transposed, pre-scaled by 1/sqrt(64)
#pragma unroll
    for (int p = 0; p < 4; p++) {
        const int d0 = lc4 + p * 16;
        float4 q4 = *(const float4*)(Qg + lr * HS + d0);
        Qs[(d0 + 0) * PAD + lr] = q4.x * 0.125f;
        Qs[(d0 + 1) * PAD + lr] = q4.y * 0.125f;
        Qs[(d0 + 2) * PAD + lr] = q4.z * 0.125f;
        Qs[(d0 + 3) * PAD + lr] = q4.w * 0.125f;
    }

    float m_i[4], l_i[4], acc[4][4];
#pragma unroll
    for (int i = 0; i < 4; i++) {
        m_i[i] = -1e30f;
        l_i[i] = 0.f;
#pragma unroll
        for (int j = 0; j < 4; j++) acc[i][j] = 0.f;
    }

    for (int kt = 0; kt <= qt; kt++) {
        // Stage K/V tile through registers, then sync (protects prev-iter reads)
        float4 kr[4], vr[4];
#pragma unroll
        for (int p = 0; p < 4; p++) {
            const int d0 = lc4 + p * 16;
            kr[p] = *(const float4*)(Kg + (size_t)(kt * 64 + lr) * HS + d0);
            vr[p] = *(const float4*)(Vg + (size_t)(kt * 64 + lr) * HS + d0);
        }
        __syncthreads();
#pragma unroll
        for (int p = 0; p < 4; p++) {
            const int d0 = lc4 + p * 16;
            Ks[(d0 + 0) * PAD + lr] = kr[p].x;
            Ks[(d0 + 1) * PAD + lr] = kr[p].y;
            Ks[(d0 + 2) * PAD + lr] = kr[p].z;
            Ks[(d0 + 3) * PAD + lr] = kr[p].w;
            *(float4*)&Vs[lr * PAD + d0] = vr[p];
        }
        __syncthreads();

        // S = Q K^T  (already scaled)
        float s[4][4];
#pragma unroll
        for (int i = 0; i < 4; i++)
#pragma unroll
            for (int j = 0; j < 4; j++) s[i][j] = 0.f;

#pragma unroll 16
        for (int d = 0; d < 64; d++) {
            float4 qa = *(const float4*)&Qs[d * PAD + ty * 4];
            float4 kb = *(const float4*)&Ks[d * PAD + tx * 4];
            float av[4] = {qa.x, qa.y, qa.z, qa.w};
            float bv[4] = {kb.x, kb.y, kb.z, kb.w};
#pragma unroll
            for (int i = 0; i < 4; i++)
#pragma unroll
                for (int j = 0; j < 4; j++)
                    s[i][j] = fmaf(av[i], bv[j], s[i][j]);
        }

        // Causal mask only on the diagonal tile
        if (kt == qt) {
#pragma unroll
            for (int i = 0; i < 4; i++)
#pragma unroll
                for (int j = 0; j < 4; j++)
                    if (tx * 4 + j > ty * 4 + i) s[i][j] = -1e9f;
        }

        // Online softmax: row stats across the 16 tx-lanes of each q row
#pragma unroll
        for (int i = 0; i < 4; i++) {
            float mt = fmaxf(fmaxf(s[i][0], s[i][1]), fmaxf(s[i][2], s[i][3]));
#pragma unroll
            for (int o = 8; o > 0; o >>= 1)
                mt = fmaxf(mt, __shfl_xor_sync(0xffffffffu, mt, o, 16));
            const float mn = fmaxf(m_i[i], mt);
            float su = 0.f;
#pragma unroll
            for (int j = 0; j < 4; j++) {
                s[i][j] = __expf(s[i][j] - mn);
                su += s[i][j];
            }
#pragma unroll
            for (int o = 8; o > 0; o >>= 1)
                su += __shfl_xor_sync(0xffffffffu, su, o, 16);
            const float alpha = __expf(m_i[i] - mn);
            l_i[i] = l_i[i] * alpha + su;
            m_i[i] = mn;
#pragma unroll
            for (int j = 0; j < 4; j++) acc[i][j] *= alpha;
        }

        // P -> smem (transposed), then acc += P V
#pragma unroll
        for (int i = 0; i < 4; i++)
#pragma unroll
            for (int j = 0; j < 4; j++)
                Ps[(tx * 4 + j) * PAD + ty * 4 + i] = s[i][j];
        __syncthreads();

#pragma unroll 16
        for (int k = 0; k < 64; k++) {
            float4 pa = *(const float4*)&Ps[k * PAD + ty * 4];
            float4 vb = *(const float4*)&Vs[k * PAD + tx * 4];
            float av[4] = {pa.x, pa.y, pa.z, pa.w};
            float bv[4] = {vb.x, vb.y, vb.z, vb.w};
#pragma unroll
            for (int i = 0; i < 4; i++)
#pragma unroll
                for (int j = 0; j < 4; j++)
                    acc[i][j] = fmaf(av[i], bv[j], acc[i][j]);
        }
        // next iteration's pre-store __syncthreads protects Vs/Ps reuse
    }

#pragma unroll
    for (int i = 0; i < 4; i++) {
        const int row  = qt * 64 + ty * 4 + i;
        const float nv = 1.f / l_i[i];
        *(float4*)&g_att[(size_t)row * DIM + head * HS + tx * 4] =
            make_float4(acc[i][0] * nv, acc[i][1] * nv, acc[i][2] * nv, acc[i][3] * nv);
    }
}

// ---------------------------------------------------------------------------
extern "C" void kernel_launch(void* const* d_in, const int* in_sizes, int n_in,
                              void* d_out, int out_size)
{
    const float* x  = (const float*)d_in[0];
    const float* wq = (const float*)d_in[1];
    const float* bq = (const float*)d_in[2];
    const float* wk = (const float*)d_in[3];
    const float* bk = (const float*)d_in[4];
    const float* wv = (const float*)d_in[5];
    const float* bv = (const float*)d_in[6];
    const float* wo = (const float*)d_in[7];
    const float* bo = (const float*)d_in[8];
    float* out = (float*)d_out;

    float *qp, *kp, *vp, *ap;
    cudaGetSymbolAddress((void**)&qp, g_q);
    cudaGetSymbolAddress((void**)&kp, g_k);
    cudaGetSymbolAddress((void**)&vp, g_v);
    cudaGetSymbolAddress((void**)&ap, g_att);

    const int attn_smem = 4 * 64 * PAD * (int)sizeof(float);  // 69632 B
    cudaFuncSetAttribute(attn_kernel, cudaFuncAttributeMaxDynamicSharedMemorySize,
                         attn_smem);

    dim3 gg(DIM / 128, SEQ / 128);   // 8 x 32
    gemm_bias_kernel<true><<<gg, 256>>>(x, wq, bq, qp);
    gemm_bias_kernel<true><<<gg, 256>>>(x, wk, bk, kp);
    gemm_bias_kernel<true><<<gg, 256>>>(x, wv, bv, vp);
    attn_kernel<<<dim3(64, NH), 256, attn_smem>>>();
    gemm_bias_kernel<false><<<gg, 256>>>(ap, wo, bo, out);
}

// round 5
// speedup vs baseline: 1.5806x; 1.5806x over previous
#include <cuda_runtime.h>
#include <cuda_bf16.h>
#include <cstdint>

#define SEQ 4096
#define DIM 1024
#define NH  16
#define HS  64

// ---------------- device scratch (no allocation allowed) -------------------
__device__ __nv_bfloat16 g_xh[SEQ * DIM],  g_xl[SEQ * DIM];
__device__ __nv_bfloat16 g_ah[SEQ * DIM],  g_al[SEQ * DIM];
__device__ __nv_bfloat16 g_wqh[DIM * DIM], g_wql[DIM * DIM];
__device__ __nv_bfloat16 g_wkh[DIM * DIM], g_wkl[DIM * DIM];
__device__ __nv_bfloat16 g_wvh[DIM * DIM], g_wvl[DIM * DIM];
__device__ __nv_bfloat16 g_woh[DIM * DIM], g_wol[DIM * DIM];
__device__ __nv_bfloat16 g_qh[NH * SEQ * HS], g_ql[NH * SEQ * HS];
__device__ __nv_bfloat16 g_kh[NH * SEQ * HS], g_kl[NH * SEQ * HS];
__device__ __nv_bfloat16 g_vh[NH * SEQ * HS], g_vl[NH * SEQ * HS];

// ---------------- helpers ---------------------------------------------------
__device__ __forceinline__ uint32_t su32(const void* p) {
    uint32_t a;
    asm("{ .reg .u64 t; cvta.to.shared.u64 t, %1; cvt.u32.u64 %0, t; }"
        : "=r"(a) : "l"(p));
    return a;
}
__device__ __forceinline__ void cpa16(uint32_t d, const void* s) {
    asm volatile("cp.async.cg.shared.global [%0], [%1], 16;" :: "r"(d), "l"(s));
}
#define CP_COMMIT() asm volatile("cp.async.commit_group;" ::: "memory")
#define CP_WAIT(n)  asm volatile("cp.async.wait_group %0;" :: "n"(n) : "memory")

__device__ __forceinline__ uint32_t lds32(uint32_t a) {
    uint32_t v;
    asm volatile("ld.shared.b32 %0, [%1];" : "=r"(v) : "r"(a));
    return v;
}
__device__ __forceinline__ void sts32(uint32_t a, uint32_t v) {
    asm volatile("st.shared.b32 [%0], %1;" :: "r"(a), "r"(v) : "memory");
}
__device__ __forceinline__ void mma16816(float (&c)[4],
                                         uint32_t a0, uint32_t a1, uint32_t a2, uint32_t a3,
                                         uint32_t b0, uint32_t b1) {
    asm volatile(
        "mma.sync.aligned.m16n8k16.row.col.f32.bf16.bf16.f32 "
        "{%0,%1,%2,%3}, {%4,%5,%6,%7}, {%8,%9}, {%0,%1,%2,%3};"
        : "+f"(c[0]), "+f"(c[1]), "+f"(c[2]), "+f"(c[3])
        : "r"(a0), "r"(a1), "r"(a2), "r"(a3), "r"(b0), "r"(b1));
}
__device__ __forceinline__ uint32_t pk(__nv_bfloat16 a, __nv_bfloat16 b) {
    __nv_bfloat162 t(a, b);            // .x = a -> low half = even k element
    return *reinterpret_cast<uint32_t*>(&t);
}

// ---------------------------------------------------------------------------
// fp32 -> bf16 hi/lo split
// ---------------------------------------------------------------------------
__global__ void conv_split(const float* __restrict__ s,
                           __nv_bfloat16* __restrict__ hi,
                           __nv_bfloat16* __restrict__ lo, int n4)
{
    int i = blockIdx.x * blockDim.x + threadIdx.x;
    if (i >= n4) return;
    float4 v = ((const float4*)s)[i];
    __nv_bfloat16 hx = __float2bfloat16(v.x), hy = __float2bfloat16(v.y);
    __nv_bfloat16 hz = __float2bfloat16(v.z), hw = __float2bfloat16(v.w);
    __nv_bfloat16 lx = __float2bfloat16(v.x - __bfloat162float(hx));
    __nv_bfloat16 ly = __float2bfloat16(v.y - __bfloat162float(hy));
    __nv_bfloat16 lz = __float2bfloat16(v.z - __bfloat162float(hz));
    __nv_bfloat16 lw = __float2bfloat16(v.w - __bfloat162float(hw));
    ((__nv_bfloat162*)hi)[2 * i]     = __nv_bfloat162(hx, hy);
    ((__nv_bfloat162*)hi)[2 * i + 1] = __nv_bfloat162(hz, hw);
    ((__nv_bfloat162*)lo)[2 * i]     = __nv_bfloat162(lx, ly);
    ((__nv_bfloat162*)lo)[2 * i + 1] = __nv_bfloat162(lz, lw);
}

// ---------------------------------------------------------------------------
// mma.sync GEMM: C = A @ W^T + bias.  A,W given as bf16 hi/lo planes.
// CTA 128x128, 256 thr = 8 warps (4 m x 2 n), warp tile 32x64.
// BK=32, cp.async double buffer.  MODE 0: fp32 out. MODE 1: bf16 hi/lo
// planes in [head][s][64] layout.
// ---------------------------------------------------------------------------
#define GSTR   40                         // smem row stride (bf16 elems), 80 B
#define GPLANE (128 * GSTR * 2)           // plane bytes = 10240
#define GSTAGE (4 * GPLANE)               // 40960
#define GEMM_SMEM (2 * GSTAGE)            // 81920

template <int MODE>
__global__ __launch_bounds__(256, 2)
void gemm_mma(const __nv_bfloat16* __restrict__ Ah, const __nv_bfloat16* __restrict__ Al,
              const __nv_bfloat16* __restrict__ Bh, const __nv_bfloat16* __restrict__ Bl,
              const float* __restrict__ bias,
              __nv_bfloat16* __restrict__ Chi, __nv_bfloat16* __restrict__ Clo,
              float* __restrict__ Cf)
{
    extern __shared__ char smc[];
    const uint32_t smb = su32(smc);
    const int tid = threadIdx.x, lane = tid & 31, wid = tid >> 5;
    const int wm = wid & 3, wn = wid >> 2;
    const int bm = blockIdx.y * 128, bn = blockIdx.x * 128;

    const __nv_bfloat16* gp[4] = {Ah, Al, Bh, Bl};
    const int gbase[4] = {bm, bm, bn, bn};

    float c[2][8][4];
#pragma unroll
    for (int mt = 0; mt < 2; mt++)
#pragma unroll
        for (int nt = 0; nt < 8; nt++)
#pragma unroll
            for (int e = 0; e < 4; e++) c[mt][nt][e] = 0.f;

    auto issue = [&](int s) {
        const uint32_t sb = smb + (s & 1) * GSTAGE;
        const int k0 = s * 32;
#pragma unroll
        for (int p = 0; p < 4; p++)
#pragma unroll
            for (int i = 0; i < 2; i++) {
                const int id = tid + i * 256;        // 0..511
                const int row = id >> 2, ch = id & 3;
                cpa16(sb + p * GPLANE + row * (GSTR * 2) + ch * 16,
                      gp[p] + (size_t)(gbase[p] + row) * DIM + k0 + ch * 8);
            }
        CP_COMMIT();
    };

    issue(0);
    const int NS = DIM / 32;
    for (int s = 0; s < NS; s++) {
        if (s + 1 < NS) { issue(s + 1); CP_WAIT(1); }
        else            { CP_WAIT(0); }
        __syncthreads();
        const uint32_t sb  = smb + (s & 1) * GSTAGE;
        const uint32_t aH = sb, aL = sb + GPLANE, bH = sb + 2 * GPLANE, bL = sb + 3 * GPLANE;
#pragma unroll
        for (int kq = 0; kq < 2; kq++) {
            uint32_t ah[2][4], al[2][4];
#pragma unroll
            for (int mt = 0; mt < 2; mt++) {
                const int r  = wm * 32 + mt * 16 + (lane >> 2);
                const uint32_t w0 = (uint32_t)(r * 80 + kq * 32 + (lane & 3) * 4);
                const uint32_t w1 = (uint32_t)((r + 8) * 80 + kq * 32 + (lane & 3) * 4);
                ah[mt][0] = lds32(aH + w0); ah[mt][1] = lds32(aH + w1);
                ah[mt][2] = lds32(aH + w0 + 16); ah[mt][3] = lds32(aH + w1 + 16);
                al[mt][0] = lds32(aL + w0); al[mt][1] = lds32(aL + w1);
                al[mt][2] = lds32(aL + w0 + 16); al[mt][3] = lds32(aL + w1 + 16);
            }
#pragma unroll
            for (int nt = 0; nt < 8; nt++) {
                const int n = wn * 64 + nt * 8 + (lane >> 2);
                const uint32_t w0 = (uint32_t)(n * 80 + kq * 32 + (lane & 3) * 4);
                const uint32_t bh0 = lds32(bH + w0), bh1 = lds32(bH + w0 + 16);
                const uint32_t bl0 = lds32(bL + w0), bl1 = lds32(bL + w0 + 16);
#pragma unroll
                for (int mt = 0; mt < 2; mt++) {
                    mma16816(c[mt][nt], ah[mt][0], ah[mt][1], ah[mt][2], ah[mt][3], bh0, bh1);
                    mma16816(c[mt][nt], ah[mt][0], ah[mt][1], ah[mt][2], ah[mt][3], bl0, bl1);
                    mma16816(c[mt][nt], al[mt][0], al[mt][1], al[mt][2], al[mt][3], bh0, bh1);
                }
            }
        }
        __syncthreads();
    }

    // epilogue: fragments -> global
#pragma unroll
    for (int mt = 0; mt < 2; mt++)
#pragma unroll
        for (int nt = 0; nt < 8; nt++) {
            const int col = bn + wn * 64 + nt * 8 + (lane & 3) * 2;
            const float b0 = bias[col], b1 = bias[col + 1];
#pragma unroll
            for (int h = 0; h < 2; h++) {
                const int row = bm + wm * 32 + mt * 16 + (lane >> 2) + h * 8;
                const float v0 = c[mt][nt][h * 2 + 0] + b0;
                const float v1 = c[mt][nt][h * 2 + 1] + b1;
                if (MODE == 1) {
                    const int head = col >> 6, off = col & 63;
                    const size_t idx = ((size_t)head * SEQ + row) * HS + off;
                    __nv_bfloat16 h0 = __float2bfloat16(v0), h1 = __float2bfloat16(v1);
                    __nv_bfloat16 l0 = __float2bfloat16(v0 - __bfloat162float(h0));
                    __nv_bfloat16 l1 = __float2bfloat16(v1 - __bfloat162float(h1));
                    *(uint32_t*)&Chi[idx] = pk(h0, h1);
                    *(uint32_t*)&Clo[idx] = pk(l0, l1);
                } else {
                    *(float2*)&Cf[(size_t)row * DIM + col] = make_float2(v0, v1);
                }
            }
        }
}

// ---------------------------------------------------------------------------
// mma.sync flash attention.  CTA = (head, 64-row q tile), 128 thr = 4 warps,
// warp owns 16 q rows.  hi/lo split for QK^T and PV.
// ---------------------------------------------------------------------------
#define APAD   72                       // bf16 elems per smem row (144 B)
#define APLANE (64 * APAD * 2)          // plane bytes = 9216
#define ATT_SMEM (6 * APLANE)           // Qh Ql Kh Kl Vh Vl = 55296

__global__ __launch_bounds__(128, 3)
void attn_mma()
{
    extern __shared__ char smc[];
    const uint32_t smb = su32(smc);
    const int tid = threadIdx.x, lane = tid & 31, wid = tid >> 5;
    const int head = blockIdx.y;
    const int qt   = 63 - blockIdx.x;

    const uint32_t sQh = smb,               sQl = smb + APLANE;
    const uint32_t sKh = smb + 2 * APLANE,  sKl = smb + 3 * APLANE;
    const uint32_t sVh = smb + 4 * APLANE,  sVl = smb + 5 * APLANE;

    const size_t hb = (size_t)head * SEQ * HS;
    const __nv_bfloat16* Qhg = g_qh + hb + (size_t)qt * 64 * HS;
    const __nv_bfloat16* Qlg = g_ql + hb + (size_t)qt * 64 * HS;
    const __nv_bfloat16* Khg = g_kh + hb;
    const __nv_bfloat16* Klg = g_kl + hb;
    const __nv_bfloat16* Vhg = g_vh + hb;
    const __nv_bfloat16* Vlg = g_vl + hb;

    // Q tile -> smem (once)
#pragma unroll
    for (int i = 0; i < 4; i++) {
        const int id = tid + i * 128, row = id >> 3, ch = id & 7;
        cpa16(sQh + row * (APAD * 2) + ch * 16, Qhg + row * HS + ch * 8);
        cpa16(sQl + row * (APAD * 2) + ch * 16, Qlg + row * HS + ch * 8);
    }
    CP_COMMIT();

    float o[8][4];
#pragma unroll
    for (int nt = 0; nt < 8; nt++)
#pragma unroll
        for (int e = 0; e < 4; e++) o[nt][e] = 0.f;
    float m_i[2] = {-1e30f, -1e30f}, l_i[2] = {0.f, 0.f};

    for (int kt = 0; kt <= qt; kt++) {
        // ---- V tile -> regs (transpose source) ----
        uint4 vh[2][2], vl[2][2];
#pragma unroll
        for (int i = 0; i < 2; i++) {
            const int id = tid + i * 128, kp = id & 31, dc = id >> 5;
            const size_t base = (size_t)(kt * 64 + 2 * kp) * HS + dc * 8;
            vh[i][0] = *(const uint4*)(Vhg + base);
            vh[i][1] = *(const uint4*)(Vhg + base + HS);
            vl[i][0] = *(const uint4*)(Vlg + base);
            vl[i][1] = *(const uint4*)(Vlg + base + HS);
        }
        __syncthreads();   // everyone done with previous K/V smem

        // ---- K tile -> smem via cp.async ----
#pragma unroll
        for (int i = 0; i < 4; i++) {
            const int id = tid + i * 128, row = id >> 3, ch = id & 7;
            const size_t src = (size_t)(kt * 64 + row) * HS + ch * 8;
            cpa16(sKh + row * (APAD * 2) + ch * 16, Khg + src);
            cpa16(sKl + row * (APAD * 2) + ch * 16, Klg + src);
        }
        CP_COMMIT();

        // ---- V transpose -> smem [d][key] ----
#pragma unroll
        for (int i = 0; i < 2; i++) {
            const int id = tid + i * 128, kp = id & 31, dc = id >> 5;
            const __nv_bfloat16* ph0 = (const __nv_bfloat16*)&vh[i][0];
            const __nv_bfloat16* ph1 = (const __nv_bfloat16*)&vh[i][1];
            const __nv_bfloat16* pl0 = (const __nv_bfloat16*)&vl[i][0];
            const __nv_bfloat16* pl1 = (const __nv_bfloat16*)&vl[i][1];
#pragma unroll
            for (int j = 0; j < 8; j++) {
                const uint32_t a = (dc * 8 + j) * (APAD * 2) + kp * 4;
                sts32(sVh + a, pk(ph0[j], ph1[j]));
                sts32(sVl + a, pk(pl0[j], pl1[j]));
            }
        }
        CP_WAIT(0);
        __syncthreads();

        // ---- S = Q K^T (split) ----
        float s[8][4];
#pragma unroll
        for (int nt = 0; nt < 8; nt++)
#pragma unroll
            for (int e = 0; e < 4; e++) s[nt][e] = 0.f;

#pragma unroll
        for (int kq = 0; kq < 4; kq++) {
            uint32_t ah[4], al[4];
            {
                const int r = wid * 16 + (lane >> 2);
                const uint32_t w0 = r * (APAD * 2) + kq * 32 + (lane & 3) * 4;
                const uint32_t w1 = (r + 8) * (APAD * 2) + kq * 32 + (lane & 3) * 4;
                ah[0] = lds32(sQh + w0); ah[1] = lds32(sQh + w1);
                ah[2] = lds32(sQh + w0 + 16); ah[3] = lds32(sQh + w1 + 16);
                al[0] = lds32(sQl + w0); al[1] = lds32(sQl + w1);
                al[2] = lds32(sQl + w0 + 16); al[3] = lds32(sQl + w1 + 16);
            }
#pragma unroll
            for (int nt = 0; nt < 8; nt++) {
                const int n = nt * 8 + (lane >> 2);
                const uint32_t w0 = n * (APAD * 2) + kq * 32 + (lane & 3) * 4;
                const uint32_t bh0 = lds32(sKh + w0), bh1 = lds32(sKh + w0 + 16);
                const uint32_t bl0 = lds32(sKl + w0), bl1 = lds32(sKl + w0 + 16);
                mma16816(s[nt], ah[0], ah[1], ah[2], ah[3], bh0, bh1);
                mma16816(s[nt], ah[0], ah[1], ah[2], ah[3], bl0, bl1);
                mma16816(s[nt], al[0], al[1], al[2], al[3], bh0, bh1);
            }
        }

        // scale + causal mask (diag tile only)
#pragma unroll
        for (int nt = 0; nt < 8; nt++)
#pragma unroll
            for (int e = 0; e < 4; e++) s[nt][e] *= 0.125f;
        if (kt == qt) {
#pragma unroll
            for (int nt = 0; nt < 8; nt++)
#pragma unroll
                for (int e = 0; e < 4; e++) {
                    const int r = wid * 16 + (lane >> 2) + (e >> 1) * 8;
                    const int cc = nt * 8 + (lane & 3) * 2 + (e & 1);
                    if (cc > r) s[nt][e] = -1e9f;
                }
        }

        // online softmax per row group (h=0: row r, h=1: row r+8)
#pragma unroll
        for (int h = 0; h < 2; h++) {
            float mt = -1e30f;
#pragma unroll
            for (int nt = 0; nt < 8; nt++)
                mt = fmaxf(mt, fmaxf(s[nt][h * 2], s[nt][h * 2 + 1]));
            mt = fmaxf(mt, __shfl_xor_sync(0xffffffffu, mt, 1));
            mt = fmaxf(mt, __shfl_xor_sync(0xffffffffu, mt, 2));
            const float mn = fmaxf(m_i[h], mt);
            float su = 0.f;
#pragma unroll
            for (int nt = 0; nt < 8; nt++) {
                s[nt][h * 2]     = __expf(s[nt][h * 2]     - mn);
                s[nt][h * 2 + 1] = __expf(s[nt][h * 2 + 1] - mn);
                su += s[nt][h * 2] + s[nt][h * 2 + 1];
            }
            su += __shfl_xor_sync(0xffffffffu, su, 1);
            su += __shfl_xor_sync(0xffffffffu, su, 2);
            const float alpha = __expf(m_i[h] - mn);
            l_i[h] = l_i[h] * alpha + su;
            m_i[h] = mn;
#pragma unroll
            for (int nt = 0; nt < 8; nt++) {
                o[nt][h * 2]     *= alpha;
                o[nt][h * 2 + 1] *= alpha;
            }
        }

        // ---- O += P V (split P, split V, drop lo*lo) ----
#pragma unroll
        for (int kq = 0; kq < 4; kq++) {
            uint32_t pah[4], pal[4];
#pragma unroll
            for (int g = 0; g < 2; g++) {         // g: which S ntile (2kq+g)
#pragma unroll
                for (int h = 0; h < 2; h++) {
                    const float p0 = s[2 * kq + g][h * 2];
                    const float p1 = s[2 * kq + g][h * 2 + 1];
                    const __nv_bfloat16 h0 = __float2bfloat16(p0);
                    const __nv_bfloat16 h1 = __float2bfloat16(p1);
                    const __nv_bfloat16 r0 = __float2bfloat16(p0 - __bfloat162float(h0));
                    const __nv_bfloat16 r1 = __float2bfloat16(p1 - __bfloat162float(h1));
                    pah[g * 2 + h] = pk(h0, h1);
                    pal[g * 2 + h] = pk(r0, r1);
                }
            }
#pragma unroll
            for (int nt = 0; nt < 8; nt++) {
                const int d = nt * 8 + (lane >> 2);
                const uint32_t w0 = d * (APAD * 2) + kq * 32 + (lane & 3) * 4;
                const uint32_t bh0 = lds32(sVh + w0), bh1 = lds32(sVh + w0 + 16);
                const uint32_t bl0 = lds32(sVl + w0), bl1 = lds32(sVl + w0 + 16);
                mma16816(o[nt], pah[0], pah[1], pah[2], pah[3], bh0, bh1);
                mma16816(o[nt], pal[0], pal[1], pal[2], pal[3], bh0, bh1);
                mma16816(o[nt], pah[0], pah[1], pah[2], pah[3], bl0, bl1);
            }
        }
    }

    // epilogue: normalize, split hi/lo, write [s][1024]
#pragma unroll
    for (int h = 0; h < 2; h++) {
        const float nv = 1.f / l_i[h];
        const int row = qt * 64 + wid * 16 + (lane >> 2) + h * 8;
#pragma unroll
        for (int nt = 0; nt < 8; nt++) {
            const int col = head * HS + nt * 8 + (lane & 3) * 2;
            const float v0 = o[nt][h * 2] * nv;
            const float v1 = o[nt][h * 2 + 1] * nv;
            const __nv_bfloat16 h0 = __float2bfloat16(v0), h1 = __float2bfloat16(v1);
            const __nv_bfloat16 l0 = __float2bfloat16(v0 - __bfloat162float(h0));
            const __nv_bfloat16 l1 = __float2bfloat16(v1 - __bfloat162float(h1));
            const size_t idx = (size_t)row * DIM + col;
            *(uint32_t*)&g_ah[idx] = pk(h0, h1);
            *(uint32_t*)&g_al[idx] = pk(l0, l1);
        }
    }
}

// ---------------------------------------------------------------------------
extern "C" void kernel_launch(void* const* d_in, const int* in_sizes, int n_in,
                              void* d_out, int out_size)
{
    const float* x  = (const float*)d_in[0];
    const float* wq = (const float*)d_in[1];
    const float* bq = (const float*)d_in[2];
    const float* wk = (const float*)d_in[3];
    const float* bk = (const float*)d_in[4];
    const float* wv = (const float*)d_in[5];
    const float* bv = (const float*)d_in[6];
    const float* wo = (const float*)d_in[7];
    const float* bo = (const float*)d_in[8];
    float* out = (float*)d_out;

    __nv_bfloat16 *xh,*xl,*ah,*al,*wqh,*wql,*wkh,*wkl,*wvh,*wvl,*woh,*wol;
    __nv_bfloat16 *qh,*ql,*kh,*kl,*vh,*vl;
    cudaGetSymbolAddress((void**)&xh,  g_xh);  cudaGetSymbolAddress((void**)&xl,  g_xl);
    cudaGetSymbolAddress((void**)&ah,  g_ah);  cudaGetSymbolAddress((void**)&al,  g_al);
    cudaGetSymbolAddress((void**)&wqh, g_wqh); cudaGetSymbolAddress((void**)&wql, g_wql);
    cudaGetSymbolAddress((void**)&wkh, g_wkh); cudaGetSymbolAddress((void**)&wkl, g_wkl);
    cudaGetSymbolAddress((void**)&wvh, g_wvh); cudaGetSymbolAddress((void**)&wvl, g_wvl);
    cudaGetSymbolAddress((void**)&woh, g_woh); cudaGetSymbolAddress((void**)&wol, g_wol);
    cudaGetSymbolAddress((void**)&qh,  g_qh);  cudaGetSymbolAddress((void**)&ql,  g_ql);
    cudaGetSymbolAddress((void**)&kh,  g_kh);  cudaGetSymbolAddress((void**)&kl,  g_kl);
    cudaGetSymbolAddress((void**)&vh,  g_vh);  cudaGetSymbolAddress((void**)&vl,  g_vl);

    cudaFuncSetAttribute(gemm_mma<0>, cudaFuncAttributeMaxDynamicSharedMemorySize, GEMM_SMEM);
    cudaFuncSetAttribute(gemm_mma<1>, cudaFuncAttributeMaxDynamicSharedMemorySize, GEMM_SMEM);
    cudaFuncSetAttribute(attn_mma,    cudaFuncAttributeMaxDynamicSharedMemorySize, ATT_SMEM);

    const int n4x = SEQ * DIM / 4, n4w = DIM * DIM / 4;
    conv_split<<<(n4x + 255) / 256, 256>>>(x,  xh,  xl,  n4x);
    conv_split<<<(n4w + 255) / 256, 256>>>(wq, wqh, wql, n4w);
    conv_split<<<(n4w + 255) / 256, 256>>>(wk, wkh, wkl, n4w);
    conv_split<<<(n4w + 255) / 256, 256>>>(wv, wvh, wvl, n4w);
    conv_split<<<(n4w + 255) / 256, 256>>>(wo, woh, wol, n4w);

    dim3 gg(DIM / 128, SEQ / 128);   // 8 x 32
    gemm_mma<1><<<gg, 256, GEMM_SMEM>>>(xh, xl, wqh, wql, bq, qh, ql, nullptr);
    gemm_mma<1><<<gg, 256, GEMM_SMEM>>>(xh, xl, wkh, wkl, bk, kh, kl, nullptr);
    gemm_mma<1><<<gg, 256, GEMM_SMEM>>>(xh, xl, wvh, wvl, bv, vh, vl, nullptr);

    attn_mma<<<dim3(64, NH), 128, ATT_SMEM>>>();

    gemm_mma<0><<<gg, 256, GEMM_SMEM>>>(ah, al, woh, wol, bo, nullptr, nullptr, out);
}

// round 7
// speedup vs baseline: 2.6391x; 1.6697x over previous
#include <cuda_runtime.h>
#include <cuda_bf16.h>
#include <cstdint>

#define SEQ 4096
#define DIM 1024
#define NH  16
#define HS  64

// ---------------- device scratch (no allocation allowed) -------------------
__device__ __nv_bfloat16 g_xh[SEQ * DIM],  g_xl[SEQ * DIM];
__device__ __nv_bfloat16 g_ah[SEQ * DIM],  g_al[SEQ * DIM];
__device__ __nv_bfloat16 g_wqh[DIM * DIM], g_wql[DIM * DIM];
__device__ __nv_bfloat16 g_wkh[DIM * DIM], g_wkl[DIM * DIM];
__device__ __nv_bfloat16 g_wvh[DIM * DIM], g_wvl[DIM * DIM];
__device__ __nv_bfloat16 g_woh[DIM * DIM], g_wol[DIM * DIM];
__device__ __nv_bfloat16 g_qh[NH * SEQ * HS], g_ql[NH * SEQ * HS];
__device__ __nv_bfloat16 g_kh[NH * SEQ * HS], g_kl[NH * SEQ * HS];
__device__ __nv_bfloat16 g_vh[NH * SEQ * HS], g_vl[NH * SEQ * HS];

// ---------------- helpers ---------------------------------------------------
__device__ __forceinline__ uint32_t su32(const void* p) {
    uint32_t a;
    asm("{ .reg .u64 t; cvta.to.shared.u64 t, %1; cvt.u32.u64 %0, t; }"
        : "=r"(a) : "l"(p));
    return a;
}
__device__ __forceinline__ void cpa16(uint32_t d, const void* s) {
    asm volatile("cp.async.cg.shared.global [%0], [%1], 16;" :: "r"(d), "l"(s));
}
#define CP_COMMIT() asm volatile("cp.async.commit_group;" ::: "memory")
#define CP_WAIT(n)  asm volatile("cp.async.wait_group %0;" :: "n"(n) : "memory")

__device__ __forceinline__ void ldsm4(uint32_t (&r)[4], uint32_t a) {
    asm volatile("ldmatrix.sync.aligned.m8n8.x4.shared.b16 {%0,%1,%2,%3}, [%4];"
        : "=r"(r[0]), "=r"(r[1]), "=r"(r[2]), "=r"(r[3]) : "r"(a));
}
__device__ __forceinline__ void ldsm4t(uint32_t (&r)[4], uint32_t a) {
    asm volatile("ldmatrix.sync.aligned.m8n8.x4.trans.shared.b16 {%0,%1,%2,%3}, [%4];"
        : "=r"(r[0]), "=r"(r[1]), "=r"(r[2]), "=r"(r[3]) : "r"(a));
}
__device__ __forceinline__ void mma16816(float (&c)[4],
                                         uint32_t a0, uint32_t a1, uint32_t a2, uint32_t a3,
                                         uint32_t b0, uint32_t b1) {
    asm volatile(
        "mma.sync.aligned.m16n8k16.row.col.f32.bf16.bf16.f32 "
        "{%0,%1,%2,%3}, {%4,%5,%6,%7}, {%8,%9}, {%0,%1,%2,%3};"
        : "+f"(c[0]), "+f"(c[1]), "+f"(c[2]), "+f"(c[3])
        : "r"(a0), "r"(a1), "r"(a2), "r"(a3), "r"(b0), "r"(b1));
}
__device__ __forceinline__ uint32_t pk(__nv_bfloat16 a, __nv_bfloat16 b) {
    __nv_bfloat162 t(a, b);
    return *reinterpret_cast<uint32_t*>(&t);
}

// ---------------------------------------------------------------------------
// fp32 -> bf16 hi/lo split
// ---------------------------------------------------------------------------
__global__ void conv_split(const float* __restrict__ s,
                           __nv_bfloat16* __restrict__ hi,
                           __nv_bfloat16* __restrict__ lo, int n4)
{
    int i = blockIdx.x * blockDim.x + threadIdx.x;
    if (i >= n4) return;
    float4 v = ((const float4*)s)[i];
    __nv_bfloat16 hx = __float2bfloat16(v.x), hy = __float2bfloat16(v.y);
    __nv_bfloat16 hz = __float2bfloat16(v.z), hw = __float2bfloat16(v.w);
    __nv_bfloat16 lx = __float2bfloat16(v.x - __bfloat162float(hx));
    __nv_bfloat16 ly = __float2bfloat16(v.y - __bfloat162float(hy));
    __nv_bfloat16 lz = __float2bfloat16(v.z - __bfloat162float(hz));
    __nv_bfloat16 lw = __float2bfloat16(v.w - __bfloat162float(hw));
    ((__nv_bfloat162*)hi)[2 * i]     = __nv_bfloat162(hx, hy);
    ((__nv_bfloat162*)hi)[2 * i + 1] = __nv_bfloat162(hz, hw);
    ((__nv_bfloat162*)lo)[2 * i]     = __nv_bfloat162(lx, ly);
    ((__nv_bfloat162*)lo)[2 * i + 1] = __nv_bfloat162(lz, lw);
}

// ---------------------------------------------------------------------------
// mma.sync GEMM with ldmatrix feed.  CTA 128x128, 8 warps (4m x 2n),
// warp tile 32x64, BK=32, cp.async double buffer.
// ---------------------------------------------------------------------------
#define GSTR_B 80
#define GPLANE (128 * GSTR_B)
#define GSTAGE (4 * GPLANE)
#define GEMM_SMEM (2 * GSTAGE)

template <int MODE>
__global__ __launch_bounds__(256, 2)
void gemm_mma(const __nv_bfloat16* __restrict__ Ah, const __nv_bfloat16* __restrict__ Al,
              const __nv_bfloat16* __restrict__ Bh, const __nv_bfloat16* __restrict__ Bl,
              const float* __restrict__ bias,
              __nv_bfloat16* __restrict__ Chi, __nv_bfloat16* __restrict__ Clo,
              float* __restrict__ Cf)
{
    extern __shared__ char smc[];
    const uint32_t smb = su32(smc);
    const int tid = threadIdx.x, lane = tid & 31, wid = tid >> 5;
    const int wm = wid & 3, wn = wid >> 2;
    const int bm = blockIdx.y * 128, bn = blockIdx.x * 128;

    const int lg = lane >> 3, lr8 = lane & 7;
    const uint32_t offG = (uint32_t)((lr8 + (lg & 1) * 8) * GSTR_B + (lg >> 1) * 16);

    const __nv_bfloat16* gp[4] = {Ah, Al, Bh, Bl};
    const int gbase[4] = {bm, bm, bn, bn};

    float c[2][8][4];
#pragma unroll
    for (int mt = 0; mt < 2; mt++)
#pragma unroll
        for (int nt = 0; nt < 8; nt++)
#pragma unroll
            for (int e = 0; e < 4; e++) c[mt][nt][e] = 0.f;

    auto issue = [&](int s) {
        const uint32_t sb = smb + (s & 1) * GSTAGE;
        const int k0 = s * 32;
#pragma unroll
        for (int p = 0; p < 4; p++)
#pragma unroll
            for (int i = 0; i < 2; i++) {
                const int id = tid + i * 256;
                const int row = id >> 2, ch = id & 3;
                cpa16(sb + p * GPLANE + row * GSTR_B + ch * 16,
                      gp[p] + (size_t)(gbase[p] + row) * DIM + k0 + ch * 8);
            }
        CP_COMMIT();
    };

    issue(0);
    const int NS = DIM / 32;
    for (int s = 0; s < NS; s++) {
        if (s + 1 < NS) { issue(s + 1); CP_WAIT(1); }
        else            { CP_WAIT(0); }
        __syncthreads();
        const uint32_t sb = smb + (s & 1) * GSTAGE;
        const uint32_t aH = sb, aL = sb + GPLANE, bH = sb + 2 * GPLANE, bL = sb + 3 * GPLANE;
#pragma unroll
        for (int kq = 0; kq < 2; kq++) {
            uint32_t afh[2][4], afl[2][4];
#pragma unroll
            for (int mt = 0; mt < 2; mt++) {
                const uint32_t rb = (uint32_t)((wm * 32 + mt * 16) * GSTR_B + kq * 32) + offG;
                ldsm4(afh[mt], aH + rb);
                ldsm4(afl[mt], aL + rb);
            }
#pragma unroll
            for (int ng = 0; ng < 4; ng++) {
                const uint32_t rb = (uint32_t)((wn * 64 + ng * 16) * GSTR_B + kq * 32) + offG;
                uint32_t bh[4], bl[4];
                ldsm4(bh, bH + rb);
                ldsm4(bl, bL + rb);
#pragma unroll
                for (int mt = 0; mt < 2; mt++) {
                    mma16816(c[mt][2*ng],   afh[mt][0],afh[mt][1],afh[mt][2],afh[mt][3], bh[0], bh[2]);
                    mma16816(c[mt][2*ng],   afh[mt][0],afh[mt][1],afh[mt][2],afh[mt][3], bl[0], bl[2]);
                    mma16816(c[mt][2*ng],   afl[mt][0],afl[mt][1],afl[mt][2],afl[mt][3], bh[0], bh[2]);
                    mma16816(c[mt][2*ng+1], afh[mt][0],afh[mt][1],afh[mt][2],afh[mt][3], bh[1], bh[3]);
                    mma16816(c[mt][2*ng+1], afh[mt][0],afh[mt][1],afh[mt][2],afh[mt][3], bl[1], bl[3]);
                    mma16816(c[mt][2*ng+1], afl[mt][0],afl[mt][1],afl[mt][2],afl[mt][3], bh[1], bh[3]);
                }
            }
        }
        __syncthreads();
    }

#pragma unroll
    for (int mt = 0; mt < 2; mt++)
#pragma unroll
        for (int nt = 0; nt < 8; nt++) {
            const int col = bn + wn * 64 + nt * 8 + (lane & 3) * 2;
            const float b0 = bias[col], b1 = bias[col + 1];
#pragma unroll
            for (int h = 0; h < 2; h++) {
                const int row = bm + wm * 32 + mt * 16 + (lane >> 2) + h * 8;
                const float v0 = c[mt][nt][h * 2 + 0] + b0;
                const float v1 = c[mt][nt][h * 2 + 1] + b1;
                if (MODE == 1) {
                    const int head = col >> 6, off = col & 63;
                    const size_t idx = ((size_t)head * SEQ + row) * HS + off;
                    __nv_bfloat16 h0 = __float2bfloat16(v0), h1 = __float2bfloat16(v1);
                    __nv_bfloat16 l0 = __float2bfloat16(v0 - __bfloat162float(h0));
                    __nv_bfloat16 l1 = __float2bfloat16(v1 - __bfloat162float(h1));
                    *(uint32_t*)&Chi[idx] = pk(h0, h1);
                    *(uint32_t*)&Clo[idx] = pk(l0, l1);
                } else {
                    *(float2*)&Cf[(size_t)row * DIM + col] = make_float2(v0, v1);
                }
            }
        }
}

// ---------------------------------------------------------------------------
// Flash attention: ldmatrix feed, ldmatrix.trans for V, double-buffered
// cp.async K/V pipeline, Q fragments hoisted into registers.
// ---------------------------------------------------------------------------
#define APAD_B  144
#define APLANE  (64 * APAD_B)
#define AST     (4 * APLANE)
#define ATT_SMEM (2 * AST)

__global__ __launch_bounds__(128, 3)
void attn_mma()
{
    extern __shared__ char smc[];
    const uint32_t smb = su32(smc);
    const int tid = threadIdx.x, lane = tid & 31, wid = tid >> 5;
    const int head = blockIdx.y;
    const int qt   = 63 - blockIdx.x;

    const int lg = lane >> 3, lr8 = lane & 7;
    const uint32_t offA = (uint32_t)((lr8 + (lg & 1) * 8) * APAD_B + (lg >> 1) * 16);
    const uint32_t offV = (uint32_t)((lr8 + (lg >> 1) * 8) * APAD_B + (lg & 1) * 16);

    const size_t hb = (size_t)head * SEQ * HS;
    const __nv_bfloat16* Qhg = g_qh + hb + (size_t)qt * 64 * HS;
    const __nv_bfloat16* Qlg = g_ql + hb + (size_t)qt * 64 * HS;
    const __nv_bfloat16* Khg = g_kh + hb;
    const __nv_bfloat16* Klg = g_kl + hb;
    const __nv_bfloat16* Vhg = g_vh + hb;
    const __nv_bfloat16* Vlg = g_vl + hb;

    // Q -> stage0 buffers, extract fragments, then reuse the space
#pragma unroll
    for (int i = 0; i < 4; i++) {
        const int id = tid + i * 128, row = id >> 3, ch = id & 7;
        cpa16(smb + 0 * APLANE + row * APAD_B + ch * 16, Qhg + row * HS + ch * 8);
        cpa16(smb + 1 * APLANE + row * APAD_B + ch * 16, Qlg + row * HS + ch * 8);
    }
    CP_COMMIT(); CP_WAIT(0);
    __syncthreads();
    uint32_t qfh[4][4], qfl[4][4];
#pragma unroll
    for (int kq = 0; kq < 4; kq++) {
        const uint32_t rb = (uint32_t)(wid * 16 * APAD_B + kq * 32) + offA;
        ldsm4(qfh[kq], smb + 0 * APLANE + rb);
        ldsm4(qfl[kq], smb + 1 * APLANE + rb);
    }
    __syncthreads();

    auto issue = [&](int kt) {
        const uint32_t sb = smb + (kt & 1) * AST;
#pragma unroll
        for (int i = 0; i < 4; i++) {
            const int id = tid + i * 128, row = id >> 3, ch = id & 7;
            const size_t src = (size_t)(kt * 64 + row) * HS + ch * 8;
            const uint32_t da = row * APAD_B + ch * 16;
            cpa16(sb + 0 * APLANE + da, Khg + src);
            cpa16(sb + 1 * APLANE + da, Klg + src);
            cpa16(sb + 2 * APLANE + da, Vhg + src);
            cpa16(sb + 3 * APLANE + da, Vlg + src);
        }
        CP_COMMIT();
    };

    issue(0);
    if (qt >= 1) issue(1);

    float o[8][4];
#pragma unroll
    for (int nt = 0; nt < 8; nt++)
#pragma unroll
        for (int e = 0; e < 4; e++) o[nt][e] = 0.f;
    float m_i[2] = {-1e30f, -1e30f}, l_i[2] = {0.f, 0.f};

    for (int kt = 0; kt <= qt; kt++) {
        if (kt < qt) CP_WAIT(1); else CP_WAIT(0);
        __syncthreads();
        const uint32_t sb  = smb + (kt & 1) * AST;
        const uint32_t sKh = sb, sKl = sb + APLANE, sVh = sb + 2 * APLANE, sVl = sb + 3 * APLANE;

        float s[8][4];
#pragma unroll
        for (int nt = 0; nt < 8; nt++)
#pragma unroll
            for (int e = 0; e < 4; e++) s[nt][e] = 0.f;

#pragma unroll
        for (int kq = 0; kq < 4; kq++) {
#pragma unroll
            for (int ng = 0; ng < 4; ng++) {
                const uint32_t rb = (uint32_t)(ng * 16 * APAD_B + kq * 32) + offA;
                uint32_t kbh[4], kbl[4];
                ldsm4(kbh, sKh + rb);
                ldsm4(kbl, sKl + rb);
                mma16816(s[2*ng],   qfh[kq][0],qfh[kq][1],qfh[kq][2],qfh[kq][3], kbh[0], kbh[2]);
                mma16816(s[2*ng],   qfh[kq][0],qfh[kq][1],qfh[kq][2],qfh[kq][3], kbl[0], kbl[2]);
                mma16816(s[2*ng],   qfl[kq][0],qfl[kq][1],qfl[kq][2],qfl[kq][3], kbh[0], kbh[2]);
                mma16816(s[2*ng+1], qfh[kq][0],qfh[kq][1],qfh[kq][2],qfh[kq][3], kbh[1], kbh[3]);
                mma16816(s[2*ng+1], qfh[kq][0],qfh[kq][1],qfh[kq][2],qfh[kq][3], kbl[1], kbl[3]);
                mma16816(s[2*ng+1], qfl[kq][0],qfl[kq][1],qfl[kq][2],qfl[kq][3], kbh[1], kbh[3]);
            }
        }

#pragma unroll
        for (int nt = 0; nt < 8; nt++)
#pragma unroll
            for (int e = 0; e < 4; e++) s[nt][e] *= 0.125f;
        if (kt == qt) {
#pragma unroll
            for (int nt = 0; nt < 8; nt++)
#pragma unroll
                for (int e = 0; e < 4; e++) {
                    const int r  = wid * 16 + (lane >> 2) + (e >> 1) * 8;
                    const int cc = nt * 8 + (lane & 3) * 2 + (e & 1);
                    if (cc > r) s[nt][e] = -1e9f;
                }
        }

#pragma unroll
        for (int h = 0; h < 2; h++) {
            float mt = -1e30f;
#pragma unroll
            for (int nt = 0; nt < 8; nt++)
                mt = fmaxf(mt, fmaxf(s[nt][h * 2], s[nt][h * 2 + 1]));
            mt = fmaxf(mt, __shfl_xor_sync(0xffffffffu, mt, 1));
            mt = fmaxf(mt, __shfl_xor_sync(0xffffffffu, mt, 2));
            const float mn = fmaxf(m_i[h], mt);
            float su = 0.f;
#pragma unroll
            for (int nt = 0; nt < 8; nt++) {
                s[nt][h * 2]     = __expf(s[nt][h * 2]     - mn);
                s[nt][h * 2 + 1] = __expf(s[nt][h * 2 + 1] - mn);
                su += s[nt][h * 2] + s[nt][h * 2 + 1];
            }
            su += __shfl_xor_sync(0xffffffffu, su, 1);
            su += __shfl_xor_sync(0xffffffffu, su, 2);
            const float alpha = __expf(m_i[h] - mn);
            l_i[h] = l_i[h] * alpha + su;
            m_i[h] = mn;
#pragma unroll
            for (int nt = 0; nt < 8; nt++) {
                o[nt][h * 2]     *= alpha;
                o[nt][h * 2 + 1] *= alpha;
            }
        }

#pragma unroll
        for (int kq = 0; kq < 4; kq++) {
            uint32_t pah[4], pal[4];
#pragma unroll
            for (int g = 0; g < 2; g++)
#pragma unroll
                for (int h = 0; h < 2; h++) {
                    const float p0 = s[2 * kq + g][h * 2];
                    const float p1 = s[2 * kq + g][h * 2 + 1];
                    const __nv_bfloat16 h0 = __float2bfloat16(p0);
                    const __nv_bfloat16 h1 = __float2bfloat16(p1);
                    const __nv_bfloat16 r0 = __float2bfloat16(p0 - __bfloat162float(h0));
                    const __nv_bfloat16 r1 = __float2bfloat16(p1 - __bfloat162float(h1));
                    pah[g * 2 + h] = pk(h0, h1);
                    pal[g * 2 + h] = pk(r0, r1);
                }
#pragma unroll
            for (int dg = 0; dg < 4; dg++) {
                const uint32_t rb = (uint32_t)(kq * 16 * APAD_B + dg * 32) + offV;
                uint32_t vbh[4], vbl[4];
                ldsm4t(vbh, sVh + rb);
                ldsm4t(vbl, sVl + rb);
                mma16816(o[2*dg],   pah[0],pah[1],pah[2],pah[3], vbh[0], vbh[2]);
                mma16816(o[2*dg],   pal[0],pal[1],pal[2],pal[3], vbh[0], vbh[2]);
                mma16816(o[2*dg],   pah[0],pah[1],pah[2],pah[3], vbl[0], vbl[2]);
                mma16816(o[2*dg+1], pah[0],pah[1],pah[2],pah[3], vbh[1], vbh[3]);
                mma16816(o[2*dg+1], pal[0],pal[1],pal[2],pal[3], vbh[1], vbh[3]);
                mma16816(o[2*dg+1], pah[0],pah[1],pah[2],pah[3], vbl[1], vbl[3]);
            }
        }
        __syncthreads();
        if (kt + 2 <= qt) issue(kt + 2);
    }

#pragma unroll
    for (int h = 0; h < 2; h++) {
        const float nv = 1.f / l_i[h];
        const int row = qt * 64 + wid * 16 + (lane >> 2) + h * 8;
#pragma unroll
        for (int nt = 0; nt < 8; nt++) {
            const int col = head * HS + nt * 8 + (lane & 3) * 2;
            const float v0 = o[nt][h * 2] * nv;
            const float v1 = o[nt][h * 2 + 1] * nv;
            const __nv_bfloat16 h0 = __float2bfloat16(v0), h1 = __float2bfloat16(v1);
            const __nv_bfloat16 l0 = __float2bfloat16(v0 - __bfloat162float(h0));
            const __nv_bfloat16 l1 = __float2bfloat16(v1 - __bfloat162float(h1));
            const size_t idx = (size_t)row * DIM + col;
            *(uint32_t*)&g_ah[idx] = pk(h0, h1);
            *(uint32_t*)&g_al[idx] = pk(l0, l1);
        }
    }
}

// ---------------------------------------------------------------------------
extern "C" void kernel_launch(void* const* d_in, const int* in_sizes, int n_in,
                              void* d_out, int out_size)
{
    const float* x  = (const float*)d_in[0];
    const float* wq = (const float*)d_in[1];
    const float* bq = (const float*)d_in[2];
    const float* wk = (const float*)d_in[3];
    const float* bk = (const float*)d_in[4];
    const float* wv = (const float*)d_in[5];
    const float* bv = (const float*)d_in[6];
    const float* wo = (const float*)d_in[7];
    const float* bo = (const float*)d_in[8];
    float* out = (float*)d_out;

    __nv_bfloat16 *xh,*xl,*ah,*al,*wqh,*wql,*wkh,*wkl,*wvh,*wvl,*woh,*wol;
    __nv_bfloat16 *qh,*ql,*kh,*kl,*vh,*vl;
    cudaGetSymbolAddress((void**)&xh,  g_xh);  cudaGetSymbolAddress((void**)&xl,  g_xl);
    cudaGetSymbolAddress((void**)&ah,  g_ah);  cudaGetSymbolAddress((void**)&al,  g_al);
    cudaGetSymbolAddress((void**)&wqh, g_wqh); cudaGetSymbolAddress((void**)&wql, g_wql);
    cudaGetSymbolAddress((void**)&wkh, g_wkh); cudaGetSymbolAddress((void**)&wkl, g_wkl);
    cudaGetSymbolAddress((void**)&wvh, g_wvh); cudaGetSymbolAddress((void**)&wvl, g_wvl);
    cudaGetSymbolAddress((void**)&woh, g_woh); cudaGetSymbolAddress((void**)&wol, g_wol);
    cudaGetSymbolAddress((void**)&qh,  g_qh);  cudaGetSymbolAddress((void**)&ql,  g_ql);
    cudaGetSymbolAddress((void**)&kh,  g_kh);  cudaGetSymbolAddress((void**)&kl,  g_kl);
    cudaGetSymbolAddress((void**)&vh,  g_vh);  cudaGetSymbolAddress((void**)&vl,  g_vl);

    cudaFuncSetAttribute(gemm_mma<0>, cudaFuncAttributeMaxDynamicSharedMemorySize, GEMM_SMEM);
    cudaFuncSetAttribute(gemm_mma<1>, cudaFuncAttributeMaxDynamicSharedMemorySize, GEMM_SMEM);
    cudaFuncSetAttribute(attn_mma,    cudaFuncAttributeMaxDynamicSharedMemorySize, ATT_SMEM);

    const int n4x = SEQ * DIM / 4, n4w = DIM * DIM / 4;
    conv_split<<<(n4x + 255) / 256, 256>>>(x,  xh,  xl,  n4x);
    conv_split<<<(n4w + 255) / 256, 256>>>(wq, wqh, wql, n4w);
    conv_split<<<(n4w + 255) / 256, 256>>>(wk, wkh, wkl, n4w);
    conv_split<<<(n4w + 255) / 256, 256>>>(wv, wvh, wvl, n4w);
    conv_split<<<(n4w + 255) / 256, 256>>>(wo, woh, wol, n4w);

    dim3 gg(DIM / 128, SEQ / 128);
    gemm_mma<1><<<gg, 256, GEMM_SMEM>>>(xh, xl, wqh, wql, bq, qh, ql, nullptr);
    gemm_mma<1><<<gg, 256, GEMM_SMEM>>>(xh, xl, wkh, wkl, bk, kh, kl, nullptr);
    gemm_mma<1><<<gg, 256, GEMM_SMEM>>>(xh, xl, wvh, wvl, bv, vh, vl, nullptr);

    attn_mma<<<dim3(64, NH), 128, ATT_SMEM>>>();

    gemm_mma<0><<<gg, 256, GEMM_SMEM>>>(ah, al, woh, wol, bo, nullptr, nullptr, out);
}